// round 7
// baseline (speedup 1.0000x reference)
#include <cuda_runtime.h>
#include <math.h>

// ---------------------------------------------------------------------------
// Binarized network, fully fused. v6b (alignment-fixed v6):
//  - 2 lanes per batch element (8 positions each); 1024 CTAs -> single wave
//  - packed uniform constant loads: uint4{w0,w1,w2,thrI} + uint2{thrL,thrR},
//    edge thresholds selected with SEL (no divergent LDC)
//  - single-LOP3 taps (immLut 0x28): (v0^w)&mb with mb=xnor(v0,vc) per block
//  - vector-loaded smem tables grouped in an aligned prefix:
//      W1a | pad4 | W1b | pad4 | W2a | pad2 | W2b   (all uint4/uint2 aligned)
// ---------------------------------------------------------------------------

struct __align__(16) CP {            // warp-uniform -> __constant__
    float c0[32][8];                 // s0..s3, conv_b, bn_m, bn_scale, bn_b
    uint4 wt[4][32];                 // {w0, w1, w2, thrI}
    uint2 lr[4][32];                 // {thrL, thrR} (phantom-adjusted)
};
struct __align__(16) SP {            // per-lane divergent -> shared
    unsigned W1a[32][20];            // fc1 outputs 0..31, row stride 20 (16B mult)
    unsigned padA[4];                // keeps W1b 16B-aligned + bank offset
    unsigned W1b[32][20];            // fc1 outputs 32..63
    unsigned padB[4];                // word 1284 -> W2a at 1288 (8B/16B aligned)
    unsigned W2a[32][2];             // fc2 outputs 0..31 (uint2 loads)
    unsigned pad2[2];
    unsigned W2b[32][2];             // fc2 outputs 32..63
    int P5a[32]; int P5b[32];
    int P6a[32]; int P6b[32];
    unsigned W3[2];
    float sig[65];
};

__device__ CP g_cp;
__device__ SP g_sp;
__constant__ CP c_cp;

// (a^b)&c as a single LOP3 (immLut 0x28)
__device__ __forceinline__ unsigned xand(unsigned a, unsigned b, unsigned c) {
    unsigned r;
    asm("lop3.b32 %0, %1, %2, %3, 0x28;" : "=r"(r) : "r"(a), "r"(b), "r"(c));
    return r;
}

__device__ __forceinline__ float bnval(float z, float cb, float m, float sc, float bb) {
    float t1 = z + cb;
    float t2 = t1 - m;
    return fmaf(t2, sc, bb);
}

// first even z in [zmin, zmax] with bnval >= 0 (monotone); zmax+2 if none
__device__ int first_nonneg_z(int zmin, int zmax, float cb, float m, float sc, float bb) {
    int lo = zmin >> 1, hi = zmax >> 1;
    int ans = hi + 1;
    while (lo <= hi) {
        int mid = lo + ((hi - lo) >> 1);
        if (bnval((float)(2 * mid), cb, m, sc, bb) >= 0.f) { ans = mid; hi = mid - 1; }
        else lo = mid + 1;
    }
    return 2 * ans;
}

__global__ void prep_kernel(
    const float* conv0_w, const float* conv0_b,
    const float* bn0_g, const float* bn0_b, const float* bn0_m, const float* bn0_v,
    const float* convs_w, const float* convs_b,
    const float* bns_g, const float* bns_b, const float* bns_m, const float* bns_v,
    const float* fc1_w, const float* fc1_b,
    const float* bn5_g, const float* bn5_b, const float* bn5_m, const float* bn5_v,
    const float* fc2_w, const float* fc2_b,
    const float* bn6_g, const float* bn6_b, const float* bn6_m, const float* bn6_v,
    const float* fc3_w, const float* fc3_b)
{
    const int t = threadIdx.x;
    const int nt = blockDim.x;

    for (int o = t; o < 32; o += nt) {
        for (int c = 0; c < 4; c++)
            g_cp.c0[o][c] = (conv0_w[o * 4 + c] >= 0.f) ? 1.f : -1.f;
        float sc = __fdiv_rn(bn0_g[o], __fsqrt_rn(bn0_v[o] + 0.01f));
        g_cp.c0[o][4] = conv0_b[o];
        g_cp.c0[o][5] = bn0_m[o];
        g_cp.c0[o][6] = sc;
        g_cp.c0[o][7] = bn0_b[o];
    }

    for (int idx = t; idx < 128; idx += nt) {
        int i = idx / 32, o = idx % 32;
        unsigned wb[3];
        for (int k = 0; k < 3; k++) {
            unsigned w = 0;
            for (int c = 0; c < 32; c++)
                if (convs_w[((i * 32 + o) * 32 + c) * 3 + k] >= 0.f) w |= 1u << c;
            wb[k] = w;
        }
        int oi = i * 32 + o;
        float cb = convs_b[oi], m = bns_m[oi], bb = bns_b[oi];
        float sc = __fdiv_rn(bns_g[oi], __fsqrt_rn(bns_v[oi] + 0.01f));
        int Ci = (i == 0) ? 96 : 192;   // planes*32*3
        int Ce = (i == 0) ? 64 : 128;   // planes*32*2
        int mult = (i == 0) ? 1 : 2;
        int zth = first_nonneg_z(-(Ci + 2), Ci + 2, cb, m, sc, bb);
        int pmi = (Ci - zth) / 2;
        int pme = (Ce - zth) / 2;
        g_cp.wt[i][o] = make_uint4(wb[0], wb[1], wb[2], (unsigned)pmi);
        g_cp.lr[i][o] = make_uint2((unsigned)(pme + mult * __popc(wb[0])),
                                   (unsigned)(pme + mult * __popc(wb[2])));
    }

    for (int idx = t; idx < 64 * 16; idx += nt) {
        int l = idx % 16, o = idx / 16;
        unsigned w = 0;
        for (int c = 0; c < 32; c++)
            if (fc1_w[o * 512 + c * 16 + l] >= 0.f) w |= 1u << c;
        if (o < 32) g_sp.W1a[o][l] = w;
        else        g_sp.W1b[o - 32][l] = w;
    }
    for (int o = t; o < 64; o += nt) {
        unsigned* row = (o < 32) ? g_sp.W1a[o] : g_sp.W1b[o - 32];
        row[16] = 0; row[17] = 0; row[18] = 0; row[19] = 0;
        float cb = fc1_b[o], m = bn5_m[o], bb = bn5_b[o];
        float sc = __fdiv_rn(bn5_g[o], __fsqrt_rn(bn5_v[o] + 0.01f));
        int zth = first_nonneg_z(-1026, 1026, cb, m, sc, bb);
        int p5 = (1024 - zth) / 2;
        if (o < 32) g_sp.P5a[o] = p5; else g_sp.P5b[o - 32] = p5;
    }

    for (int o = t; o < 64; o += nt) {
        for (int j = 0; j < 2; j++) {
            unsigned w = 0;
            for (int c = 0; c < 32; c++)
                if (fc2_w[o * 64 + j * 32 + c] >= 0.f) w |= 1u << c;
            if (o < 32) g_sp.W2a[o][j] = w; else g_sp.W2b[o - 32][j] = w;
        }
        float cb = fc2_b[o], m = bn6_m[o], bb = bn6_b[o];
        float sc = __fdiv_rn(bn6_g[o], __fsqrt_rn(bn6_v[o] + 0.01f));
        int zth = first_nonneg_z(-66, 66, cb, m, sc, bb);
        int p6 = (64 - zth) / 2;
        if (o < 32) g_sp.P6a[o] = p6; else g_sp.P6b[o - 32] = p6;
    }

    if (t < 2) {
        unsigned w = 0;
        for (int c = 0; c < 32; c++)
            if (fc3_w[t * 32 + c] >= 0.f) w |= 1u << c;
        g_sp.W3[t] = w;
    }
    for (int p = t; p < 65; p += nt) {
        float d = (float)(64 - 2 * p) + fc3_b[0];
        g_sp.sig[p] = 1.f / (1.f + expf(-d));
    }
}

#define NT 128

__global__ __launch_bounds__(NT, 7) void bnn_kernel(
    const float* __restrict__ x, float* __restrict__ out, int B)
{
    __shared__ SP sp;
    {
        const int n = (int)(sizeof(SP) / 4);
        const int* src = (const int*)&g_sp;
        int* dst = (int*)&sp;
        for (int i = threadIdx.x; i < n; i += NT) dst[i] = src[i];
    }
    __syncthreads();

    int gt = blockIdx.x * NT + threadIdx.x;
    int e = gt >> 1;
    int half = gt & 1;              // 0: positions 0-7, 1: positions 8-15
    if (e >= B) return;
    const bool lo = (half == 0);
    const unsigned FULL = 0xffffffffu;

    // ---- conv0 + bn0 + sign -> v0[1..8] ----------------------------------
    unsigned v0[10];
#pragma unroll
    for (int k = 0; k < 10; k++) v0[k] = 0;
    {
        float xc[4][8];
        const float4* xp = (const float4*)(x + (size_t)e * 64 + half * 8);
#pragma unroll
        for (int c = 0; c < 4; c++) {
            float4 a = xp[c * 4 + 0];
            float4 d = xp[c * 4 + 1];
            xc[c][0] = a.x; xc[c][1] = a.y; xc[c][2] = a.z; xc[c][3] = a.w;
            xc[c][4] = d.x; xc[c][5] = d.y; xc[c][6] = d.z; xc[c][7] = d.w;
        }
        unsigned mask = 1u;
#pragma unroll 4
        for (int o = 0; o < 32; o++) {
            float4 pA = *(const float4*)&c_cp.c0[o][0];
            float4 pB = *(const float4*)&c_cp.c0[o][4];
#pragma unroll
            for (int j = 0; j < 8; j++) {
                float y = pA.x * xc[0][j];
                y = fmaf(pA.y, xc[1][j], y);
                y = fmaf(pA.z, xc[2][j], y);
                y = fmaf(pA.w, xc[3][j], y);
                float t1 = y + pB.x;
                float t2 = t1 - pB.y;
                float v = fmaf(t2, pB.z, pB.w);
                if (v >= 0.f) v0[j + 1] |= mask;
            }
            mask <<= 1;
        }
    }
    // halo for s0 plane (phantom zeros at outer edges)
    {
        unsigned send = lo ? v0[8] : v0[1];
        unsigned recv = __shfl_xor_sync(FULL, send, 1);
        v0[0] = lo ? 0u : recv;
        v0[9] = lo ? recv : 0u;
    }

    // ---- block 0: single plane --------------------------------------------
    unsigned vc[10], un[8];
    vc[0] = 0; vc[9] = 0;
#pragma unroll
    for (int j = 0; j < 8; j++) un[j] = 0;
    {
        unsigned mask = 1u;
#pragma unroll 4
        for (int o = 0; o < 32; o++) {
            uint4 wt = c_cp.wt[0][o];
            uint2 lr = c_cp.lr[0][o];
            int ti = (int)wt.w;
            int tf = lo ? (int)lr.x : ti;     // left edge only on lane 0, j==0
            int tl = lo ? ti : (int)lr.y;     // right edge only on lane 1, j==7
#pragma unroll
            for (int j = 0; j < 8; j++) {
                int P = __popc(v0[j] ^ wt.x) + __popc(v0[j + 1] ^ wt.y)
                      + __popc(v0[j + 2] ^ wt.z);
                int thr = (j == 0) ? tf : (j == 7) ? tl : ti;
                if (P <= thr) un[j] |= mask;
            }
            mask <<= 1;
        }
    }
#pragma unroll
    for (int j = 0; j < 8; j++) vc[j + 1] = un[j];

    // ---- blocks 1..3: two planes, masked-tap carry-save --------------------
#pragma unroll 1
    for (int i = 1; i < 4; i++) {
        {
            unsigned send = lo ? vc[8] : vc[1];
            unsigned recv = __shfl_xor_sync(FULL, send, 1);
            vc[0] = lo ? 0u : recv;
            vc[9] = lo ? recv : 0u;
        }
        unsigned mb[10];
        int DI[8];
        {
            int pm[10];
#pragma unroll
            for (int k = 0; k < 10; k++) {
                mb[k] = ~(v0[k] ^ vc[k]);     // xnor: phantom words -> ~0
                pm[k] = __popc(mb[k]);
            }
#pragma unroll
            for (int j = 0; j < 8; j++) DI[j] = 96 - (pm[j] + pm[j + 1] + pm[j + 2]);
        }
#pragma unroll
        for (int j = 0; j < 8; j++) un[j] = 0;
        unsigned mask = 1u;
#pragma unroll 4
        for (int o = 0; o < 32; o++) {
            uint4 wt = c_cp.wt[i][o];
            uint2 lr = c_cp.lr[i][o];
            int ti = (int)wt.w;
            int tf = lo ? (int)lr.x : ti;
            int tl = lo ? ti : (int)lr.y;
#pragma unroll
            for (int j = 0; j < 8; j++) {
                int Pc = __popc(xand(v0[j],     wt.x, mb[j]))
                       + __popc(xand(v0[j + 1], wt.y, mb[j + 1]))
                       + __popc(xand(v0[j + 2], wt.z, mb[j + 2]));
                int thr = (j == 0) ? tf : (j == 7) ? tl : ti;
                if (2 * Pc + DI[j] <= thr) un[j] |= mask;
            }
            mask <<= 1;
        }
#pragma unroll
        for (int j = 0; j < 8; j++) vc[j + 1] = un[j];
    }

    // ---- final planes: own-half f0/mb, exchange other half -----------------
    unsigned f0[16], mbf[16];
    int Dsum;
    {
        unsigned mOwn[8];
        int pms = 0;
#pragma unroll
        for (int j = 0; j < 8; j++) {
            mOwn[j] = ~(v0[j + 1] ^ vc[j + 1]);
            pms += __popc(mOwn[j]);
        }
        pms += __shfl_xor_sync(FULL, pms, 1);
        Dsum = 512 - pms;
#pragma unroll
        for (int j = 0; j < 8; j++) {
            unsigned o0 = __shfl_xor_sync(FULL, v0[j + 1], 1);
            unsigned om = __shfl_xor_sync(FULL, mOwn[j], 1);
            f0[j]      = lo ? v0[j + 1] : o0;
            f0[j + 8]  = lo ? o0        : v0[j + 1];
            mbf[j]     = lo ? mOwn[j]   : om;
            mbf[j + 8] = lo ? om        : mOwn[j];
        }
    }

    // ---- fc1: 32 outputs per lane (o = half*32 + oo), carry-save ------------
    const unsigned (*W1)[20] = lo ? sp.W1a : sp.W1b;
    const int* P5 = lo ? sp.P5a : sp.P5b;
    unsigned hb = 0;
#pragma unroll 2
    for (int oo = 0; oo < 32; oo++) {
        const uint4* wv = (const uint4*)&W1[oo][0];
        int Pc = 0;
#pragma unroll
        for (int c = 0; c < 4; c++) {
            uint4 W = wv[c];
            Pc += __popc(xand(f0[4 * c + 0], W.x, mbf[4 * c + 0]))
                + __popc(xand(f0[4 * c + 1], W.y, mbf[4 * c + 1]))
                + __popc(xand(f0[4 * c + 2], W.z, mbf[4 * c + 2]))
                + __popc(xand(f0[4 * c + 3], W.w, mbf[4 * c + 3]));
        }
        if (2 * Pc + Dsum <= P5[oo]) hb |= 1u << oo;
    }
    unsigned hbo = __shfl_xor_sync(FULL, hb, 1);
    unsigned hw0 = lo ? hb : hbo;     // h bits for outputs 0..31
    unsigned hw1 = lo ? hbo : hb;     // h bits for outputs 32..63

    // ---- fc2: 32 outputs per lane -------------------------------------------
    const unsigned (*W2)[2] = lo ? sp.W2a : sp.W2b;
    const int* P6 = lo ? sp.P6a : sp.P6b;
    unsigned gb = 0;
#pragma unroll 4
    for (int oo = 0; oo < 32; oo++) {
        uint2 W = *(const uint2*)&W2[oo][0];
        int P = __popc(hw0 ^ W.x) + __popc(hw1 ^ W.y);
        if (P <= P6[oo]) gb |= 1u << oo;
    }
    unsigned gbo = __shfl_xor_sync(FULL, gb, 1);

    // ---- fc3 + sigmoid LUT ----------------------------------------------------
    if (lo) {
        int p3 = __popc(gb ^ sp.W3[0]) + __popc(gbo ^ sp.W3[1]);
        out[e] = sp.sig[p3];
    }
}

extern "C" void kernel_launch(void* const* d_in, const int* in_sizes, int n_in,
                              void* d_out, int out_size)
{
    const float* x       = (const float*)d_in[0];
    const float* conv0_w = (const float*)d_in[1];
    const float* conv0_b = (const float*)d_in[2];
    const float* bn0_g   = (const float*)d_in[3];
    const float* bn0_b   = (const float*)d_in[4];
    const float* bn0_m   = (const float*)d_in[5];
    const float* bn0_v   = (const float*)d_in[6];
    const float* convs_w = (const float*)d_in[7];
    const float* convs_b = (const float*)d_in[8];
    const float* bns_g   = (const float*)d_in[9];
    const float* bns_b   = (const float*)d_in[10];
    const float* bns_m   = (const float*)d_in[11];
    const float* bns_v   = (const float*)d_in[12];
    const float* fc1_w   = (const float*)d_in[13];
    const float* fc1_b   = (const float*)d_in[14];
    const float* bn5_g   = (const float*)d_in[15];
    const float* bn5_b   = (const float*)d_in[16];
    const float* bn5_m   = (const float*)d_in[17];
    const float* bn5_v   = (const float*)d_in[18];
    const float* fc2_w   = (const float*)d_in[19];
    const float* fc2_b   = (const float*)d_in[20];
    const float* bn6_g   = (const float*)d_in[21];
    const float* bn6_b   = (const float*)d_in[22];
    const float* bn6_m   = (const float*)d_in[23];
    const float* bn6_v   = (const float*)d_in[24];
    const float* fc3_w   = (const float*)d_in[25];
    const float* fc3_b   = (const float*)d_in[26];

    int B = in_sizes[0] / 64;   // (B, 4, 16)
    float* out = (float*)d_out;

    prep_kernel<<<1, 256>>>(conv0_w, conv0_b, bn0_g, bn0_b, bn0_m, bn0_v,
                            convs_w, convs_b, bns_g, bns_b, bns_m, bns_v,
                            fc1_w, fc1_b, bn5_g, bn5_b, bn5_m, bn5_v,
                            fc2_w, fc2_b, bn6_g, bn6_b, bn6_m, bn6_v,
                            fc3_w, fc3_b);

    void* srcp = nullptr;
    cudaGetSymbolAddress(&srcp, g_cp);
    cudaMemcpyToSymbolAsync(c_cp, srcp, sizeof(CP), 0, cudaMemcpyDeviceToDevice, 0);

    long long totalThreads = 2LL * B;
    int blocks = (int)((totalThreads + NT - 1) / NT);
    bnn_kernel<<<blocks, NT>>>(x, out, B);
}

// round 8
// speedup vs baseline: 1.0206x; 1.0206x over previous
#include <cuda_runtime.h>
#include <math.h>

// ---------------------------------------------------------------------------
// Binarized network, fully fused. v7:
//  - 4 lanes per element: ph = position half (8 pos) x oh = channel half (16 ch)
//    -> 8192 warps (~32/SM) with v6b-level total instruction count
//  - ALL tables in shared memory, bank-group-offset sections so the divergent
//    (oh / sub) accesses are conflict-free multi-broadcasts (no divergent LDC)
//  - single-LOP3 taps (immLut 0x28), carry-save two-plane popcounts,
//    phantom-edge thresholds, natural-order fc sections (no permutation)
// ---------------------------------------------------------------------------

// word-offset-audited layout (see pads): every uint4 16B-aligned, uint2 8B,
// A/B twin sections land in different bank groups (mod-32 verified).
struct __align__(16) SPK {
    float4   c0A[32];      // w0    oh=0: [oo*2+{0:pA,1:pB}]
    float4   pad0;         // w128
    float4   c0B[32];      // w132  oh=1
    float4   pad1;         // w260
    uint4    wtA[64];      // w264  [i*16+oo] {w0,w1,w2,thrI}, channels 0..15
    uint4    pad2;         // w520
    uint4    wtB[64];      // w524  channels 16..31
    uint2    lrA[64];      // w780  [i*16+oo] {thrL,thrR}
    uint2    pad3;         // w908
    uint2    lrB[64];      // w910
    uint2    pad4;         // w1038
    unsigned W1[1296];     // w1040 section s*324 + r*20 + l  (fc1 out s*16+r)
    int      P5[68];       // w2336 s*17 + r
    uint2    W2[68];       // w2404 s*17 + r   {bits vs h0..31, bits vs h32..63}
    int      P6[68];       // w2540 s*17 + r
    unsigned W3[2];        // w2608
    float    sig[66];      // w2610
};

__device__ SPK g_spk;

// (a^b)&c as a single LOP3 (immLut 0x28)
__device__ __forceinline__ unsigned xand(unsigned a, unsigned b, unsigned c) {
    unsigned r;
    asm("lop3.b32 %0, %1, %2, %3, 0x28;" : "=r"(r) : "r"(a), "r"(b), "r"(c));
    return r;
}

__device__ __forceinline__ float bnval(float z, float cb, float m, float sc, float bb) {
    float t1 = z + cb;
    float t2 = t1 - m;
    return fmaf(t2, sc, bb);
}

// first even z in [zmin, zmax] with bnval >= 0 (monotone); zmax+2 if none
__device__ int first_nonneg_z(int zmin, int zmax, float cb, float m, float sc, float bb) {
    int lo = zmin >> 1, hi = zmax >> 1;
    int ans = hi + 1;
    while (lo <= hi) {
        int mid = lo + ((hi - lo) >> 1);
        if (bnval((float)(2 * mid), cb, m, sc, bb) >= 0.f) { ans = mid; hi = mid - 1; }
        else lo = mid + 1;
    }
    return 2 * ans;
}

__global__ void prep_kernel(
    const float* conv0_w, const float* conv0_b,
    const float* bn0_g, const float* bn0_b, const float* bn0_m, const float* bn0_v,
    const float* convs_w, const float* convs_b,
    const float* bns_g, const float* bns_b, const float* bns_m, const float* bns_v,
    const float* fc1_w, const float* fc1_b,
    const float* bn5_g, const float* bn5_b, const float* bn5_m, const float* bn5_v,
    const float* fc2_w, const float* fc2_b,
    const float* bn6_g, const float* bn6_b, const float* bn6_m, const float* bn6_v,
    const float* fc3_w, const float* fc3_b)
{
    const int t = threadIdx.x;
    const int nt = blockDim.x;

    // zero entire table (covers all pads)
    {
        unsigned* p = (unsigned*)&g_spk;
        const int n = (int)(sizeof(SPK) / 4);
        for (int i = t; i < n; i += nt) p[i] = 0;
    }
    __syncthreads();

    // conv0 params
    for (int o = t; o < 32; o += nt) {
        float4 a, b;
        a.x = (conv0_w[o * 4 + 0] >= 0.f) ? 1.f : -1.f;
        a.y = (conv0_w[o * 4 + 1] >= 0.f) ? 1.f : -1.f;
        a.z = (conv0_w[o * 4 + 2] >= 0.f) ? 1.f : -1.f;
        a.w = (conv0_w[o * 4 + 3] >= 0.f) ? 1.f : -1.f;
        float sc = __fdiv_rn(bn0_g[o], __fsqrt_rn(bn0_v[o] + 0.01f));
        b.x = conv0_b[o]; b.y = bn0_m[o]; b.z = sc; b.w = bn0_b[o];
        int oo = o & 15;
        if (o < 16) { g_spk.c0A[oo * 2] = a; g_spk.c0A[oo * 2 + 1] = b; }
        else        { g_spk.c0B[oo * 2] = a; g_spk.c0B[oo * 2 + 1] = b; }
    }

    // conv block weights + integer thresholds
    for (int idx = t; idx < 128; idx += nt) {
        int i = idx / 32, o = idx % 32;
        unsigned wb[3];
        for (int k = 0; k < 3; k++) {
            unsigned w = 0;
            for (int c = 0; c < 32; c++)
                if (convs_w[((i * 32 + o) * 32 + c) * 3 + k] >= 0.f) w |= 1u << c;
            wb[k] = w;
        }
        int oi = i * 32 + o;
        float cb = convs_b[oi], m = bns_m[oi], bb = bns_b[oi];
        float sc = __fdiv_rn(bns_g[oi], __fsqrt_rn(bns_v[oi] + 0.01f));
        int Ci = (i == 0) ? 96 : 192;   // planes*32*3
        int Ce = (i == 0) ? 64 : 128;   // planes*32*2
        int mult = (i == 0) ? 1 : 2;
        int zth = first_nonneg_z(-(Ci + 2), Ci + 2, cb, m, sc, bb);
        int pmi = (Ci - zth) / 2;
        int pme = (Ce - zth) / 2;
        uint4 wt = make_uint4(wb[0], wb[1], wb[2], (unsigned)pmi);
        uint2 lr = make_uint2((unsigned)(pme + mult * __popc(wb[0])),
                              (unsigned)(pme + mult * __popc(wb[2])));
        int oo = o & 15;
        if (o < 16) { g_spk.wtA[i * 16 + oo] = wt; g_spk.lrA[i * 16 + oo] = lr; }
        else        { g_spk.wtB[i * 16 + oo] = wt; g_spk.lrB[i * 16 + oo] = lr; }
    }

    // fc1 weights into sections: out o -> section o>>4, row o&15
    for (int idx = t; idx < 64 * 16; idx += nt) {
        int l = idx % 16, o = idx / 16;
        unsigned w = 0;
        for (int c = 0; c < 32; c++)
            if (fc1_w[o * 512 + c * 16 + l] >= 0.f) w |= 1u << c;
        g_spk.W1[(o >> 4) * 324 + (o & 15) * 20 + l] = w;
    }
    for (int o = t; o < 64; o += nt) {
        float cb = fc1_b[o], m = bn5_m[o], bb = bn5_b[o];
        float sc = __fdiv_rn(bn5_g[o], __fsqrt_rn(bn5_v[o] + 0.01f));
        int zth = first_nonneg_z(-1026, 1026, cb, m, sc, bb);
        g_spk.P5[(o >> 4) * 17 + (o & 15)] = (1024 - zth) / 2;
    }

    // fc2
    for (int o = t; o < 64; o += nt) {
        unsigned w0 = 0, w1 = 0;
        for (int c = 0; c < 32; c++) {
            if (fc2_w[o * 64 + c] >= 0.f)      w0 |= 1u << c;
            if (fc2_w[o * 64 + 32 + c] >= 0.f) w1 |= 1u << c;
        }
        g_spk.W2[(o >> 4) * 17 + (o & 15)] = make_uint2(w0, w1);
        float cb = fc2_b[o], m = bn6_m[o], bb = bn6_b[o];
        float sc = __fdiv_rn(bn6_g[o], __fsqrt_rn(bn6_v[o] + 0.01f));
        int zth = first_nonneg_z(-66, 66, cb, m, sc, bb);
        g_spk.P6[(o >> 4) * 17 + (o & 15)] = (64 - zth) / 2;
    }

    // fc3 + sigmoid LUT
    if (t < 2) {
        unsigned w = 0;
        for (int c = 0; c < 32; c++)
            if (fc3_w[t * 32 + c] >= 0.f) w |= 1u << c;
        g_spk.W3[t] = w;
    }
    for (int p = t; p < 65; p += nt) {
        float d = (float)(64 - 2 * p) + fc3_b[0];
        g_spk.sig[p] = 1.f / (1.f + expf(-d));
    }
}

#define NT 128

__global__ __launch_bounds__(NT, 8) void bnn_kernel(
    const float* __restrict__ x, float* __restrict__ out, int B)
{
    __shared__ SPK sp;
    {
        const int n = (int)(sizeof(SPK) / 4);
        const unsigned* src = (const unsigned*)&g_spk;
        unsigned* dst = (unsigned*)&sp;
        for (int i = threadIdx.x; i < n; i += NT) dst[i] = src[i];
    }
    __syncthreads();

    int gt = blockIdx.x * NT + threadIdx.x;
    int e = gt >> 2;
    int sub = gt & 3;
    int ph = sub & 1;               // 0: positions 0-7, 1: positions 8-15
    int ohi = sub >> 1;             // 0: channels 0-15, 1: channels 16-31
    if (e >= B) return;
    const bool lo = (ph == 0);
    const unsigned FULL = 0xffffffffu;

    const float4* c0p = ohi ? sp.c0B : sp.c0A;
    const uint4*  wtp = ohi ? sp.wtB : sp.wtA;
    const uint2*  lrp = ohi ? sp.lrB : sp.lrA;

    // ---- conv0 + bn0 + sign: my 16 channels, my 8 positions -----------------
    unsigned v0[10];
#pragma unroll
    for (int k = 0; k < 10; k++) v0[k] = 0;
    {
        float xc[4][8];
        const float4* xp = (const float4*)(x + (size_t)e * 64 + ph * 8);
#pragma unroll
        for (int c = 0; c < 4; c++) {
            float4 a = xp[c * 4 + 0];
            float4 d = xp[c * 4 + 1];
            xc[c][0] = a.x; xc[c][1] = a.y; xc[c][2] = a.z; xc[c][3] = a.w;
            xc[c][4] = d.x; xc[c][5] = d.y; xc[c][6] = d.z; xc[c][7] = d.w;
        }
        unsigned mask = 1u;
#pragma unroll 4
        for (int oo = 0; oo < 16; oo++) {
            float4 pA = c0p[oo * 2];
            float4 pB = c0p[oo * 2 + 1];
#pragma unroll
            for (int j = 0; j < 8; j++) {
                float y = pA.x * xc[0][j];
                y = fmaf(pA.y, xc[1][j], y);
                y = fmaf(pA.z, xc[2][j], y);
                y = fmaf(pA.w, xc[3][j], y);
                float t1 = y + pB.x;
                float t2 = t1 - pB.y;
                float v = fmaf(t2, pB.z, pB.w);
                if (v >= 0.f) v0[j + 1] |= mask;
            }
            mask <<= 1;
        }
    }
    // merge with channel partner -> full 32-channel words
#pragma unroll
    for (int j = 1; j <= 8; j++) {
        unsigned other = __shfl_xor_sync(FULL, v0[j], 2);
        unsigned lo16 = ohi ? other : v0[j];
        unsigned hi16 = ohi ? v0[j] : other;
        v0[j] = lo16 | (hi16 << 16);
    }
    // position halo (phantom zeros at outer edges)
    {
        unsigned send = lo ? v0[8] : v0[1];
        unsigned recv = __shfl_xor_sync(FULL, send, 1);
        v0[0] = lo ? 0u : recv;
        v0[9] = lo ? recv : 0u;
    }

    // ---- block 0: single plane ----------------------------------------------
    unsigned vc[10], un[8];
    vc[0] = 0; vc[9] = 0;
#pragma unroll
    for (int j = 0; j < 8; j++) un[j] = 0;
    {
        unsigned mask = 1u;
#pragma unroll 4
        for (int oo = 0; oo < 16; oo++) {
            uint4 wt = wtp[oo];
            uint2 lr = lrp[oo];
            int ti = (int)wt.w;
            int tf = lo ? (int)lr.x : ti;     // left edge: ph=0, j=0
            int tl = lo ? ti : (int)lr.y;     // right edge: ph=1, j=7
#pragma unroll
            for (int j = 0; j < 8; j++) {
                int P = __popc(v0[j] ^ wt.x) + __popc(v0[j + 1] ^ wt.y)
                      + __popc(v0[j + 2] ^ wt.z);
                int thr = (j == 0) ? tf : (j == 7) ? tl : ti;
                if (P <= thr) un[j] |= mask;
            }
            mask <<= 1;
        }
    }
    // merge channel halves + set up halo
#pragma unroll
    for (int j = 0; j < 8; j++) {
        unsigned other = __shfl_xor_sync(FULL, un[j], 2);
        unsigned lo16 = ohi ? other : un[j];
        unsigned hi16 = ohi ? un[j] : other;
        vc[j + 1] = lo16 | (hi16 << 16);
    }

    // ---- blocks 1..3: two planes, masked-tap carry-save -----------------------
#pragma unroll 1
    for (int i = 1; i < 4; i++) {
        {
            unsigned send = lo ? vc[8] : vc[1];
            unsigned recv = __shfl_xor_sync(FULL, send, 1);
            vc[0] = lo ? 0u : recv;
            vc[9] = lo ? recv : 0u;
        }
        unsigned mb[10];
        int DI[8];
        {
            int pm[10];
#pragma unroll
            for (int k = 0; k < 10; k++) {
                mb[k] = ~(v0[k] ^ vc[k]);     // xnor: phantom words -> ~0
                pm[k] = __popc(mb[k]);
            }
#pragma unroll
            for (int j = 0; j < 8; j++) DI[j] = 96 - (pm[j] + pm[j + 1] + pm[j + 2]);
        }
#pragma unroll
        for (int j = 0; j < 8; j++) un[j] = 0;
        unsigned mask = 1u;
#pragma unroll 4
        for (int oo = 0; oo < 16; oo++) {
            uint4 wt = wtp[i * 16 + oo];
            uint2 lr = lrp[i * 16 + oo];
            int ti = (int)wt.w;
            int tf = lo ? (int)lr.x : ti;
            int tl = lo ? ti : (int)lr.y;
#pragma unroll
            for (int j = 0; j < 8; j++) {
                int Pc = __popc(xand(v0[j],     wt.x, mb[j]))
                       + __popc(xand(v0[j + 1], wt.y, mb[j + 1]))
                       + __popc(xand(v0[j + 2], wt.z, mb[j + 2]));
                int thr = (j == 0) ? tf : (j == 7) ? tl : ti;
                if (2 * Pc + DI[j] <= thr) un[j] |= mask;
            }
            mask <<= 1;
        }
#pragma unroll
        for (int j = 0; j < 8; j++) {
            unsigned other = __shfl_xor_sync(FULL, un[j], 2);
            unsigned lo16 = ohi ? other : un[j];
            unsigned hi16 = ohi ? un[j] : other;
            vc[j + 1] = lo16 | (hi16 << 16);
        }
    }

    // ---- final planes: own-half f0/mb, exchange position half ------------------
    unsigned f0[16], mbf[16];
    int Dsum;
    {
        unsigned mOwn[8];
        int pms = 0;
#pragma unroll
        for (int j = 0; j < 8; j++) {
            mOwn[j] = ~(v0[j + 1] ^ vc[j + 1]);
            pms += __popc(mOwn[j]);
        }
        pms += __shfl_xor_sync(FULL, pms, 1);
        Dsum = 512 - pms;
#pragma unroll
        for (int j = 0; j < 8; j++) {
            unsigned o0 = __shfl_xor_sync(FULL, v0[j + 1], 1);
            unsigned om = __shfl_xor_sync(FULL, mOwn[j], 1);
            f0[j]      = lo ? v0[j + 1] : o0;
            f0[j + 8]  = lo ? o0        : v0[j + 1];
            mbf[j]     = lo ? mOwn[j]   : om;
            mbf[j + 8] = lo ? om        : mOwn[j];
        }
    }

    // ---- fc1: 16 outputs per lane (o = sub*16 + oo), carry-save -----------------
    const unsigned* W1s = &sp.W1[sub * 324];
    const int* P5s = &sp.P5[sub * 17];
    unsigned hb = 0;
#pragma unroll 2
    for (int oo = 0; oo < 16; oo++) {
        const uint4* wv = (const uint4*)&W1s[oo * 20];
        int Pc = 0;
#pragma unroll
        for (int c = 0; c < 4; c++) {
            uint4 W = wv[c];
            Pc += __popc(xand(f0[4 * c + 0], W.x, mbf[4 * c + 0]))
                + __popc(xand(f0[4 * c + 1], W.y, mbf[4 * c + 1]))
                + __popc(xand(f0[4 * c + 2], W.z, mbf[4 * c + 2]))
                + __popc(xand(f0[4 * c + 3], W.w, mbf[4 * c + 3]));
        }
        if (2 * Pc + Dsum <= P5s[oo]) hb |= 1u << oo;
    }
    // assemble h words (natural order): hw0 = outputs 0..31, hw1 = 32..63
    unsigned t1 = __shfl_xor_sync(FULL, hb, 1);
    unsigned pw = (sub & 1) ? (t1 | (hb << 16)) : (hb | (t1 << 16));
    unsigned t2 = __shfl_xor_sync(FULL, pw, 2);
    unsigned hw0 = (sub < 2) ? pw : t2;
    unsigned hw1 = (sub < 2) ? t2 : pw;

    // ---- fc2: 16 outputs per lane -------------------------------------------------
    const uint2* W2s = &sp.W2[sub * 17];
    const int* P6s = &sp.P6[sub * 17];
    unsigned gb = 0;
#pragma unroll 4
    for (int oo = 0; oo < 16; oo++) {
        uint2 W = W2s[oo];
        int P = __popc(hw0 ^ W.x) + __popc(hw1 ^ W.y);
        if (P <= P6s[oo]) gb |= 1u << oo;
    }
    t1 = __shfl_xor_sync(FULL, gb, 1);
    pw = (sub & 1) ? (t1 | (gb << 16)) : (gb | (t1 << 16));
    t2 = __shfl_xor_sync(FULL, pw, 2);
    unsigned gw0 = (sub < 2) ? pw : t2;
    unsigned gw1 = (sub < 2) ? t2 : pw;

    // ---- fc3 + sigmoid LUT --------------------------------------------------------
    if (sub == 0) {
        int p3 = __popc(gw0 ^ sp.W3[0]) + __popc(gw1 ^ sp.W3[1]);
        out[e] = sp.sig[p3];
    }
}

extern "C" void kernel_launch(void* const* d_in, const int* in_sizes, int n_in,
                              void* d_out, int out_size)
{
    const float* x       = (const float*)d_in[0];
    const float* conv0_w = (const float*)d_in[1];
    const float* conv0_b = (const float*)d_in[2];
    const float* bn0_g   = (const float*)d_in[3];
    const float* bn0_b   = (const float*)d_in[4];
    const float* bn0_m   = (const float*)d_in[5];
    const float* bn0_v   = (const float*)d_in[6];
    const float* convs_w = (const float*)d_in[7];
    const float* convs_b = (const float*)d_in[8];
    const float* bns_g   = (const float*)d_in[9];
    const float* bns_b   = (const float*)d_in[10];
    const float* bns_m   = (const float*)d_in[11];
    const float* bns_v   = (const float*)d_in[12];
    const float* fc1_w   = (const float*)d_in[13];
    const float* fc1_b   = (const float*)d_in[14];
    const float* bn5_g   = (const float*)d_in[15];
    const float* bn5_b   = (const float*)d_in[16];
    const float* bn5_m   = (const float*)d_in[17];
    const float* bn5_v   = (const float*)d_in[18];
    const float* fc2_w   = (const float*)d_in[19];
    const float* fc2_b   = (const float*)d_in[20];
    const float* bn6_g   = (const float*)d_in[21];
    const float* bn6_b   = (const float*)d_in[22];
    const float* bn6_m   = (const float*)d_in[23];
    const float* bn6_v   = (const float*)d_in[24];
    const float* fc3_w   = (const float*)d_in[25];
    const float* fc3_b   = (const float*)d_in[26];

    int B = in_sizes[0] / 64;   // (B, 4, 16)
    float* out = (float*)d_out;

    prep_kernel<<<1, 256>>>(conv0_w, conv0_b, bn0_g, bn0_b, bn0_m, bn0_v,
                            convs_w, convs_b, bns_g, bns_b, bns_m, bns_v,
                            fc1_w, fc1_b, bn5_g, bn5_b, bn5_m, bn5_v,
                            fc2_w, fc2_b, bn6_g, bn6_b, bn6_m, bn6_v,
                            fc3_w, fc3_b);

    long long totalThreads = 4LL * B;
    int blocks = (int)((totalThreads + NT - 1) / NT);
    bnn_kernel<<<blocks, NT>>>(x, out, B);
}